// round 9
// baseline (speedup 1.0000x reference)
#include <cuda_runtime.h>
#include <cuda_bf16.h>
#include <math.h>
#include <stdint.h>

// Problem constants
#define B_   64
#define T_   2048
#define E_   512
#define R_   1024
#define A_   128
#define F_   32
#define KW   31
#define PADW 15
#define KIM  62
#define KTOT 576
#define KC2  64          // original-K per chunk
#define NCK  9           // 576/64
#define TM   128         // t rows per block
#define NPART 16         // T_/TM

#define RSW  68          // smem row stride in words (bank-perfect frag LDS)
#define RSB  272         // row stride bytes
#define ATILE (128 * RSB)   // 34816

typedef unsigned long long u64;

// Scratch (device globals; no allocations allowed)
__device__ float g_pq[B_ * A_];
__device__ __align__(16) float g_Wt[A_ * KTOT];   // W^T, tf32-rounded fp32: [a][k]
__device__ float g_align[B_ * T_];
__device__ float g_part[NPART * B_ * E_];

// ---- dynamic smem layout ----
#define OFF_A0  0
#define OFF_A1  34816
#define OFF_B   69632
#define OFF_PQ  104448
#define OFF_V   104960
#define OFF_AL  105472
#define OFF_EN  105984           // 4 x 128 x 4B
#define SMEM_SZ 108032           // x2 CTA = 216064 <= 228KB/SM

__device__ __forceinline__ uint32_t smem_u32(const void* p) {
    uint32_t a;
    asm("{ .reg .u64 t; cvta.to.shared.u64 t, %1; cvt.u32.u64 %0, t; }" : "=r"(a) : "l"(p));
    return a;
}
// accurate tanh: 1 - 2/(e^{2x}+1) via ex2.approx + rcp.approx (~1e-6 rel)
__device__ __forceinline__ float tanh_fast(float x) {
    float e;
    asm("ex2.approx.f32 %0, %1;" : "=f"(e) : "f"(x * 2.885390081777927f));
    float r;
    asm("rcp.approx.f32 %0, %1;" : "=f"(r) : "f"(e + 1.0f));
    return fmaf(-2.0f, r, 1.0f);
}
__device__ __forceinline__ uint32_t f2tf(float x) {
    uint32_t r;
    asm("cvt.rna.tf32.f32 %0, %1;" : "=r"(r) : "f"(x));
    return r;
}
__device__ __forceinline__ void mma_tf32(float* c, const uint32_t* a, uint32_t b0, uint32_t b1) {
    asm volatile(
        "mma.sync.aligned.m16n8k8.row.col.f32.tf32.tf32.f32 "
        "{%0,%1,%2,%3}, {%4,%5,%6,%7}, {%8,%9}, {%0,%1,%2,%3};"
        : "+f"(c[0]), "+f"(c[1]), "+f"(c[2]), "+f"(c[3])
        : "r"(a[0]), "r"(a[1]), "r"(a[2]), "r"(a[3]), "r"(b0), "r"(b1));
}

// ---------------- pq = attention_hidden @ W_query : (B, A) ----------------
__global__ void k_pq(const float* __restrict__ hid, const float* __restrict__ Wq) {
    __shared__ float sh[R_];
    int b = blockIdx.x, tid = threadIdx.x;
    for (int i = tid; i < R_; i += 128) sh[i] = hid[b * R_ + i];
    __syncthreads();
    float acc = 0.f;
#pragma unroll 8
    for (int r = 0; r < R_; r++) acc += sh[r] * Wq[r * A_ + tid];
    g_pq[b * A_ + tid] = acc;
}

// ---- Wcat^T tf32-rounded: k<512 = W_memory, 512..573 = conv.W_loc, rest 0 ----
__global__ void k_wcat(const float* __restrict__ Wm, const float* __restrict__ cw,
                       const float* __restrict__ Wl) {
    int row = blockIdx.x;  // k: 0..575
    int a = threadIdx.x;   // 0..127
    float v = 0.f;
    if (row < E_) {
        v = Wm[row * A_ + a];
    } else if (row < E_ + KIM) {
        int ck = row - E_;
        int c = ck / KW, k = ck - c * KW;
#pragma unroll
        for (int f = 0; f < F_; f++)
            v += cw[f * (2 * KW) + c * KW + k] * Wl[f * A_ + a];
    }
    g_Wt[a * KTOT + row] = __uint_as_float(f2tf(v));
}

// ---------------- main: mma.sync tf32 single-pass GEMM + epilogue + fused GEMV ----------------
__global__ void __launch_bounds__(256, 2)
k_main(const float* __restrict__ mem, const float* __restrict__ aw,
       const int* __restrict__ mask, const float* __restrict__ vw,
       const float* __restrict__ vb) {
    extern __shared__ char smc[];
    uint32_t sb = smem_u32(smc);
    (void)sb;
    int tid = threadIdx.x;
    int l = tid & 31, w = tid >> 5;
    int wa = w & 3, wt = w >> 2;      // warp tile: 64t (wt) x 32a (wa)
    int b = blockIdx.y, tb = blockIdx.x * TM;
    int q = l >> 2, m = l & 3;

    if (tid < A_) {
        ((float*)(smc + OFF_PQ))[tid] = g_pq[b * A_ + tid];
        ((float*)(smc + OFF_V))[tid]  = vw[tid];
    }

    float acc[4][4][4];
#pragma unroll
    for (int i = 0; i < 4; i++)
#pragma unroll
        for (int j = 0; j < 4; j++)
#pragma unroll
            for (int k = 0; k < 4; k++) acc[i][j][k] = 0.f;

    const float* memB = mem + ((size_t)b * T_ + tb) * E_;
    const float* awB  = aw + (size_t)b * 2 * T_;

    // conversion mapping: 256 threads -> 128 rows x 2 k-halves of 32
    int crow = tid >> 1, chalf = (tid & 1) * 32;
    const float* aCvtBase = memB + (size_t)crow * E_ + chalf;
    uint32_t cvtDstBase = (uint32_t)crow * RSB + (uint32_t)chalf * 4u;

    // fragment base addresses (bytes within tile)
    uint32_t aBase = (uint32_t)(wt * 64 + q) * RSB + (uint32_t)m * 4u;
    uint32_t bBase = (uint32_t)(wa * 32 + q) * RSB + (uint32_t)m * 4u;

// load 8 raw A values of chunk (cc), unit (uu), into float dst[8]
#define LOADA8(dst, cc, uu) do {                                                \
    if ((cc) < 8) {                                                             \
        const float4* p_ = (const float4*)(aCvtBase + (cc) * KC2 + (uu) * 8);   \
        float4 v0_ = p_[0], v1_ = p_[1];                                        \
        dst[0]=v0_.x; dst[1]=v0_.y; dst[2]=v0_.z; dst[3]=v0_.w;                 \
        dst[4]=v1_.x; dst[5]=v1_.y; dst[6]=v1_.z; dst[7]=v1_.w;                 \
    } else {                                                                    \
        _Pragma("unroll")                                                       \
        for (int j_ = 0; j_ < 8; j_++) {                                        \
            int kk_ = chalf + (uu) * 8 + j_;                                    \
            float v_ = 0.f;                                                     \
            if (kk_ < KIM) {                                                    \
                int ci_ = (kk_ >= KW) ? 1 : 0;                                  \
                int kp_ = kk_ - ci_ * KW;                                       \
                int tg_ = tb + crow + kp_ - PADW;                               \
                if (tg_ >= 0 && tg_ < T_) v_ = awB[ci_ * T_ + tg_];             \
            }                                                                   \
            dst[j_] = v_;                                                       \
        }                                                                       \
    }                                                                           \
} while (0)

// tf32-round 8 floats and store as 2 float4 into buffer at tile base (bufOff)
#define CVTSTORE(src, uu, bufOff) do {                                          \
    uint32_t t_[8];                                                             \
    _Pragma("unroll")                                                           \
    for (int p_ = 0; p_ < 8; p_++) t_[p_] = f2tf(src[p_]);                      \
    uint32_t d_ = (bufOff) + cvtDstBase + (uint32_t)(uu) * 32u;                 \
    *(uint4*)(smc + d_)      = make_uint4(t_[0], t_[1], t_[2], t_[3]);          \
    *(uint4*)(smc + d_ + 16) = make_uint4(t_[4], t_[5], t_[6], t_[7]);          \
} while (0)

// B copy for chunk (cc): 128 a-rows x 64 k (tf32-rounded fp32, L2-hot)
#define BCOPY(cc) do {                                                          \
    const float* bs_ = g_Wt + (size_t)crow * KTOT + (cc) * KC2 + chalf;         \
    uint32_t bd_ = OFF_B + cvtDstBase;                                          \
    _Pragma("unroll")                                                           \
    for (int i_ = 0; i_ < 4; i_++) {                                            \
        float4 v0_ = *(const float4*)(bs_ + i_ * 8);                            \
        float4 v1_ = *(const float4*)(bs_ + i_ * 8 + 4);                        \
        *(float4*)(smc + bd_ + i_ * 32)      = v0_;                             \
        *(float4*)(smc + bd_ + i_ * 32 + 16) = v1_;                             \
    }                                                                           \
} while (0)

    // ---- prologue: B(0) copy + convert A(0) into buf0 ----
    BCOPY(0);
    {
        float p0[8];
#pragma unroll
        for (int u = 0; u < 4; u++) {
            LOADA8(p0, 0, u);
            CVTSTORE(p0, u, OFF_A0);
        }
    }
    __syncthreads();

#pragma unroll 1
    for (int c = 0; c < NCK; c++) {
        uint32_t cur = (c & 1) ? OFF_A1 : OFF_A0;
        uint32_t nxt = (c & 1) ? OFF_A0 : OFF_A1;
        int doCvt = (c + 1 < NCK);

        float p0[8], p1[8];
        if (doCvt) LOADA8(p0, c + 1, 0);

        // ---- compute (8 k-steps as 4 macro) + interleaved convert of chunk c+1 ----
#pragma unroll
        for (int ss = 0; ss < 4; ss++) {
            if (doCvt && ss < 3) LOADA8(p1, c + 1, ss + 1);
#pragma unroll
            for (int s2 = 0; s2 < 2; s2++) {
                int s = 2 * ss + s2;
                uint32_t bstep = bBase + (uint32_t)s * 32u;
                uint32_t bf[8];
#pragma unroll
                for (int nj = 0; nj < 4; nj++) {
                    bf[2 * nj]     = *(const uint32_t*)(smc + OFF_B + bstep + nj * 2176u);
                    bf[2 * nj + 1] = *(const uint32_t*)(smc + OFF_B + bstep + nj * 2176u + 16u);
                }
                uint32_t astep = cur + aBase + (uint32_t)s * 32u;
#pragma unroll
                for (int mi = 0; mi < 4; mi++) {
                    uint32_t af[4];
                    const char* ap = smc + astep + mi * 4352u;
                    af[0] = *(const uint32_t*)(ap);
                    af[1] = *(const uint32_t*)(ap + 2176);
                    af[2] = *(const uint32_t*)(ap + 16);
                    af[3] = *(const uint32_t*)(ap + 2192);
                    mma_tf32(acc[mi][0], af, bf[0], bf[1]);
                    mma_tf32(acc[mi][1], af, bf[2], bf[3]);
                    mma_tf32(acc[mi][2], af, bf[4], bf[5]);
                    mma_tf32(acc[mi][3], af, bf[6], bf[7]);
                }
            }
            if (doCvt) {
                CVTSTORE(p0, ss, nxt);
                if (ss < 3) {
#pragma unroll
                    for (int j = 0; j < 8; j++) p0[j] = p1[j];
                }
            }
        }
        __syncthreads();   // A(c+1) tile complete; compute(c) done
        if (doCvt) {
            BCOPY(c + 1);
            __syncthreads();
        }
    }
#undef LOADA8
#undef CVTSTORE
#undef BCOPY

    // ---- epilogue: en[t] = sum_a v[a] * tanh(D[t,a] + pq[a]) ----
    {
        const float* sPQ = (const float*)(smc + OFF_PQ);
        const float* sV  = (const float*)(smc + OFF_V);
        float* sEn = (float*)(smc + OFF_EN);   // [4 wa][128 t]
#pragma unroll
        for (int mi = 0; mi < 4; mi++) {
            float en1 = 0.f, en2 = 0.f;
#pragma unroll
            for (int nj = 0; nj < 4; nj++) {
                int a0 = wa * 32 + nj * 8 + 2 * m;
                float v0 = sV[a0], v1 = sV[a0 + 1];
                float q0 = sPQ[a0], q1 = sPQ[a0 + 1];
                en1 += v0 * tanh_fast(acc[mi][nj][0] + q0) + v1 * tanh_fast(acc[mi][nj][1] + q1);
                en2 += v0 * tanh_fast(acc[mi][nj][2] + q0) + v1 * tanh_fast(acc[mi][nj][3] + q1);
            }
            en1 += __shfl_xor_sync(0xffffffffu, en1, 1);
            en1 += __shfl_xor_sync(0xffffffffu, en1, 2);
            en2 += __shfl_xor_sync(0xffffffffu, en2, 1);
            en2 += __shfl_xor_sync(0xffffffffu, en2, 2);
            if (m == 0) {
                int r1 = wt * 64 + mi * 16 + q;
                sEn[wa * TM + r1] = en1;
                sEn[wa * TM + r1 + 8] = en2;
            }
        }
    }
    __syncthreads();
    if (tid < TM) {
        float* sEn = (float*)(smc + OFF_EN);
        float al = sEn[tid] + sEn[TM + tid] + sEn[2 * TM + tid] + sEn[3 * TM + tid] + vb[0];
        if (mask[b * T_ + tb + tid]) al += -1e25f;
        g_align[b * T_ + tb + tid] = al;
        ((float*)(smc + OFF_AL))[tid] = al;
    }
    __syncthreads();

    // ---- fused output GEMV partials: part[e] = sum_t align[t] * mem[b,tb+t,e] ----
    {
        const float* sAl = (const float*)(smc + OFF_AL);
        int e2 = tid * 2;
        float a0 = 0.f, a1 = 0.f;
        const float* mp = memB + e2;
#pragma unroll 8
        for (int t = 0; t < TM; t++) {
            float al = sAl[t];
            float2 mv = *(const float2*)(mp + (size_t)t * E_);
            a0 = fmaf(al, mv.x, a0);
            a1 = fmaf(al, mv.y, a1);
        }
        float2 res; res.x = a0; res.y = a1;
        *(float2*)(g_part + (size_t)blockIdx.x * (B_ * E_) + b * E_ + e2) = res;
    }
}

// ---------------- softmax over T per batch -> attention_weights ----------------
__global__ void k_softmax(float* __restrict__ outw) {
    __shared__ float sE[T_];
    __shared__ float red[256];
    int b = blockIdx.x, tid = threadIdx.x;
    float mx = -3.4e38f;
    for (int i = tid; i < T_; i += 256) {
        float v = g_align[b * T_ + i];
        sE[i] = v;
        mx = fmaxf(mx, v);
    }
    red[tid] = mx;
    __syncthreads();
    for (int s = 128; s > 0; s >>= 1) {
        if (tid < s) red[tid] = fmaxf(red[tid], red[tid + s]);
        __syncthreads();
    }
    mx = red[0];
    __syncthreads();
    float sum = 0.f;
    for (int i = tid; i < T_; i += 256) {
        float ev = expf(sE[i] - mx);
        sE[i] = ev;
        sum += ev;
    }
    red[tid] = sum;
    __syncthreads();
    for (int s = 128; s > 0; s >>= 1) {
        if (tid < s) red[tid] += red[tid + s];
        __syncthreads();
    }
    float inv = 1.f / red[0];
    for (int i = tid; i < T_; i += 256) outw[b * T_ + i] = sE[i] * inv;
}

// ---------------- reduce GEMV partials ----------------
__global__ void k_reduce(float* __restrict__ outa) {
    int b = blockIdx.x, e = threadIdx.x;
    float s = 0.f;
#pragma unroll
    for (int p = 0; p < NPART; p++) s += g_part[(size_t)p * (B_ * E_) + b * E_ + e];
    outa[b * E_ + e] = s;
}

// ---------------- launch ----------------
extern "C" void kernel_launch(void* const* d_in, const int* in_sizes, int n_in,
                              void* d_out, int out_size) {
    (void)in_sizes; (void)n_in; (void)out_size;
    const float* hid  = (const float*)d_in[0];  // (B, R)
    const float* mem  = (const float*)d_in[1];  // (B, T, E)
    const float* aw   = (const float*)d_in[2];  // (B, 2, T)
    const int*   mask = (const int*)d_in[3];    // (B, T)
    const float* Wq   = (const float*)d_in[4];  // (R, A)
    const float* Wm   = (const float*)d_in[5];  // (E, A)
    const float* cw   = (const float*)d_in[6];  // (F, 2, K)
    const float* Wl   = (const float*)d_in[7];  // (F, A)
    const float* vw   = (const float*)d_in[8];  // (A,)
    const float* vb   = (const float*)d_in[9];  // (1,)

    float* out      = (float*)d_out;
    float* out_attn = out;              // (B, E)
    float* out_w    = out + B_ * E_;    // (B, T)

    static int configured = 0;
    if (!configured) {
        cudaFuncSetAttribute(k_main, cudaFuncAttributeMaxDynamicSharedMemorySize, SMEM_SZ);
        configured = 1;
    }

    k_pq<<<B_, 128>>>(hid, Wq);
    k_wcat<<<KTOT, 128>>>(Wm, cw, Wl);
    dim3 gm(T_ / TM, B_);
    k_main<<<gm, 256, SMEM_SZ>>>(mem, aw, mask, vw, vb);
    k_softmax<<<B_, 256>>>(out_w);
    k_reduce<<<B_, E_>>>(out_attn);
}

// round 10
// speedup vs baseline: 1.5566x; 1.5566x over previous
#include <cuda_runtime.h>
#include <cuda_fp16.h>
#include <math.h>
#include <stdint.h>

// Problem constants
#define B_   64
#define T_   2048
#define E_   512
#define R_   1024
#define A_   128
#define F_   32
#define KW   31
#define PADW 15
#define KIM  62
#define KTOT 576
#define KC2  64          // original-K per chunk
#define NCK  9           // 576/64
#define TM   128         // t rows per block
#define NPART 16         // T_/TM

typedef unsigned long long u64;

// Scratch (device globals; no allocations allowed)
__device__ float g_pq[B_ * A_];
__device__ __align__(16) __half g_Wh[A_ * KTOT];   // W^T fp16: [a][k]
__device__ float g_align[B_ * T_];
__device__ float g_part[NPART * B_ * E_];

// ---- dynamic smem layout: double-buffered A, single B (fp16) ----
#define OFF_A0  0
#define OFF_A1  16384
#define OFF_B   32768
#define OFF_PQ  49152
#define OFF_V   49664
#define OFF_AL  50176
#define OFF_EN  50688            // 4 x 128 x 4B
#define SMEM_SZ 52736

__device__ __forceinline__ uint32_t smem_u32(const void* p) {
    uint32_t a;
    asm("{ .reg .u64 t; cvta.to.shared.u64 t, %1; cvt.u32.u64 %0, t; }" : "=r"(a) : "l"(p));
    return a;
}
// accurate tanh: 1 - 2/(e^{2x}+1) via ex2.approx + rcp.approx (~1e-6 rel)
__device__ __forceinline__ float tanh_fast(float x) {
    float e;
    asm("ex2.approx.f32 %0, %1;" : "=f"(e) : "f"(x * 2.885390081777927f));
    float r;
    asm("rcp.approx.f32 %0, %1;" : "=f"(r) : "f"(e + 1.0f));
    return fmaf(-2.0f, r, 1.0f);
}
__device__ __forceinline__ void ldsm4(uint32_t addr, uint32_t& r0, uint32_t& r1,
                                      uint32_t& r2, uint32_t& r3) {
    asm volatile("ldmatrix.sync.aligned.m8n8.x4.shared.b16 {%0,%1,%2,%3}, [%4];"
                 : "=r"(r0), "=r"(r1), "=r"(r2), "=r"(r3) : "r"(addr));
}
__device__ __forceinline__ void mma16816h(float* c, const uint32_t* a, uint32_t b0, uint32_t b1) {
    asm volatile(
        "mma.sync.aligned.m16n8k16.row.col.f32.f16.f16.f32 "
        "{%0,%1,%2,%3}, {%4,%5,%6,%7}, {%8,%9}, {%0,%1,%2,%3};"
        : "+f"(c[0]), "+f"(c[1]), "+f"(c[2]), "+f"(c[3])
        : "r"(a[0]), "r"(a[1]), "r"(a[2]), "r"(a[3]), "r"(b0), "r"(b1));
}
// pack two f32 -> f16x2: low half = x0, high half = x1
__device__ __forceinline__ uint32_t cvt_h2(float x1, float x0) {
    uint32_t r;
    asm("cvt.rn.f16x2.f32 %0, %1, %2;" : "=r"(r) : "f"(x1), "f"(x0));
    return r;
}

// ---------------- pq = attention_hidden @ W_query : (B, A) ----------------
__global__ void k_pq(const float* __restrict__ hid, const float* __restrict__ Wq) {
    __shared__ float sh[R_];
    int b = blockIdx.x, tid = threadIdx.x;
    for (int i = tid; i < R_; i += 128) sh[i] = hid[b * R_ + i];
    __syncthreads();
    float acc = 0.f;
#pragma unroll 8
    for (int r = 0; r < R_; r++) acc += sh[r] * Wq[r * A_ + tid];
    g_pq[b * A_ + tid] = acc;
}

// ---- Wcat^T fp16: k<512 = W_memory, 512..573 = conv.W_loc, rest 0 ----
__global__ void k_wcat(const float* __restrict__ Wm, const float* __restrict__ cw,
                       const float* __restrict__ Wl) {
    int row = blockIdx.x;  // k: 0..575
    int a = threadIdx.x;   // 0..127
    float v = 0.f;
    if (row < E_) {
        v = Wm[row * A_ + a];
    } else if (row < E_ + KIM) {
        int ck = row - E_;
        int c = ck / KW, k = ck - c * KW;
#pragma unroll
        for (int f = 0; f < F_; f++)
            v += cw[f * (2 * KW) + c * KW + k] * Wl[f * A_ + a];
    }
    g_Wh[a * KTOT + row] = __float2half_rn(v);
}

// ---------------- main: mma.sync fp16 single-pass GEMM + epilogue + fused GEMV ----------------
__global__ void __launch_bounds__(256, 2)
k_main(const float* __restrict__ mem, const float* __restrict__ aw,
       const int* __restrict__ mask, const float* __restrict__ vw,
       const float* __restrict__ vb) {
    extern __shared__ char smc[];
    uint32_t sb = smem_u32(smc);
    int tid = threadIdx.x;
    int l = tid & 31, w = tid >> 5;
    int wa = w & 3, wt = w >> 2;      // warp tile: 64t (wt) x 32a (wa)
    int b = blockIdx.y, tb = blockIdx.x * TM;

    if (tid < A_) {
        ((float*)(smc + OFF_PQ))[tid] = g_pq[b * A_ + tid];
        ((float*)(smc + OFF_V))[tid]  = vw[tid];
    }

    float acc[4][4][4];
#pragma unroll
    for (int i = 0; i < 4; i++)
#pragma unroll
        for (int j = 0; j < 4; j++)
#pragma unroll
            for (int k = 0; k < 4; k++) acc[i][j][k] = 0.f;

    const float* memB = mem + ((size_t)b * T_ + tb) * E_;
    const float* awB  = aw + (size_t)b * 2 * T_;

    // conversion mapping: 256 threads -> 128 rows x 2 k-halves of 32
    int crow = tid >> 1, chalf = (tid & 1) * 32;
    uint32_t cRowBase = (uint32_t)crow * 128u;
    int cSwz = crow & 7;
    const float* aCvtBase = memB + (size_t)crow * E_ + chalf;

    // ldmatrix lane constants
    int rowA = wt * 64 + (l & 15);
    uint32_t aRowBase = (uint32_t)rowA * 128u;
    int aSwz = rowA & 7;
    int kpA = (l >> 4) & 1;
    int nB = wa * 32 + ((l & 16) >> 1) + (l & 7);
    uint32_t bRowBase = (uint32_t)nB * 128u;
    int bSwz = l & 7;
    int kpB = (l >> 3) & 1;

// load 8 raw A values of chunk (cc), unit (uu), into float dst[8]
#define LOADA8(dst, cc, uu) do {                                                \
    if ((cc) < 8) {                                                             \
        const float4* p_ = (const float4*)(aCvtBase + (cc) * KC2 + (uu) * 8);   \
        float4 v0_ = p_[0], v1_ = p_[1];                                        \
        dst[0]=v0_.x; dst[1]=v0_.y; dst[2]=v0_.z; dst[3]=v0_.w;                 \
        dst[4]=v1_.x; dst[5]=v1_.y; dst[6]=v1_.z; dst[7]=v1_.w;                 \
    } else {                                                                    \
        _Pragma("unroll")                                                       \
        for (int j_ = 0; j_ < 8; j_++) {                                        \
            int kk_ = chalf + (uu) * 8 + j_;                                    \
            float v_ = 0.f;                                                     \
            if (kk_ < KIM) {                                                    \
                int ci_ = (kk_ >= KW) ? 1 : 0;                                  \
                int kp_ = kk_ - ci_ * KW;                                       \
                int tg_ = tb + crow + kp_ - PADW;                               \
                if (tg_ >= 0 && tg_ < T_) v_ = awB[ci_ * T_ + tg_];             \
            }                                                                   \
            dst[j_] = v_;                                                       \
        }                                                                       \
    }                                                                           \
} while (0)

// convert 8 floats to fp16 and store swizzled into buffer at base (bufOff)
#define CVTSTORE(src, uu, bufOff) do {                                          \
    uint32_t h_[4];                                                             \
    _Pragma("unroll")                                                           \
    for (int p_ = 0; p_ < 4; p_++)                                              \
        h_[p_] = cvt_h2(src[2 * p_ + 1], src[2 * p_]);                          \
    int q_ = (chalf >> 3) + (uu);                                               \
    uint32_t off_ = cRowBase + (uint32_t)((q_ ^ cSwz) << 4);                    \
    *(uint4*)(smc + (bufOff) + off_) = make_uint4(h_[0], h_[1], h_[2], h_[3]);  \
} while (0)

// B copy for chunk (cc): 128 a-rows x 64 k fp16, swizzled (L2-hot)
#define BCOPY(cc) do {                                                          \
    _Pragma("unroll")                                                           \
    for (int i_ = 0; i_ < 4; i_++) {                                            \
        int idx_ = i_ * 256 + tid;                                              \
        int n_ = idx_ >> 3, q_ = idx_ & 7;                                      \
        uint32_t off_ = (uint32_t)n_ * 128u + (uint32_t)(((q_ ^ (n_ & 7)) << 4)); \
        const char* sh_ = (const char*)g_Wh + (size_t)n_ * (KTOT * 2) + (cc) * 128 + q_ * 16; \
        *(uint4*)(smc + OFF_B + off_) = *(const uint4*)sh_;                     \
    }                                                                           \
} while (0)

    // ---- prologue: B(0) copy + convert A(0) into buf0 ----
    BCOPY(0);
    {
        float p0[8];
#pragma unroll
        for (int u = 0; u < 4; u++) {
            LOADA8(p0, 0, u);
            CVTSTORE(p0, u, OFF_A0);
        }
    }
    __syncthreads();

#pragma unroll 1
    for (int c = 0; c < NCK; c++) {
        uint32_t cur = (c & 1) ? OFF_A1 : OFF_A0;
        uint32_t nxt = (c & 1) ? OFF_A0 : OFF_A1;
        int doCvt = (c + 1 < NCK);

        float p0[8], p1[8];
        if (doCvt) LOADA8(p0, c + 1, 0);

        // ---- compute + interleaved convert of chunk c+1 ----
#pragma unroll
        for (int s = 0; s < 4; s++) {
            if (doCvt && s < 3) LOADA8(p1, c + 1, s + 1);
            uint32_t bh[8];
            uint32_t kbB = (uint32_t)((((2 * s + kpB) ^ bSwz) << 4));
            ldsm4(sb + OFF_B + bRowBase + kbB,          bh[0], bh[1], bh[2], bh[3]);
            ldsm4(sb + OFF_B + bRowBase + 2048u + kbB,  bh[4], bh[5], bh[6], bh[7]);
            uint32_t kbA = (uint32_t)((((2 * s + kpA) ^ aSwz) << 4));
#pragma unroll
            for (int mi = 0; mi < 4; mi++) {
                uint32_t ah[4];
                ldsm4(sb + cur + aRowBase + mi * 2048u + kbA, ah[0], ah[1], ah[2], ah[3]);
                mma16816h(acc[mi][0], ah, bh[0], bh[1]);
                mma16816h(acc[mi][1], ah, bh[2], bh[3]);
                mma16816h(acc[mi][2], ah, bh[4], bh[5]);
                mma16816h(acc[mi][3], ah, bh[6], bh[7]);
            }
            if (doCvt) {
                CVTSTORE(p0, s, nxt);
                if (s < 3) {
#pragma unroll
                    for (int j = 0; j < 8; j++) p0[j] = p1[j];
                }
            }
        }
        __syncthreads();   // A(c+1) tile complete; compute(c) done
        if (doCvt) {
            BCOPY(c + 1);
            __syncthreads();
        }
    }
#undef LOADA8
#undef CVTSTORE
#undef BCOPY

    // ---- epilogue: en[t] = sum_a v[a] * tanh(D[t,a] + pq[a]) ----
    {
        const float* sPQ = (const float*)(smc + OFF_PQ);
        const float* sV  = (const float*)(smc + OFF_V);
        float* sEn = (float*)(smc + OFF_EN);   // [4 wa][128 t]
#pragma unroll
        for (int mi = 0; mi < 4; mi++) {
            float en1 = 0.f, en2 = 0.f;
#pragma unroll
            for (int nj = 0; nj < 4; nj++) {
                int a0 = wa * 32 + nj * 8 + 2 * (l & 3);
                float v0 = sV[a0], v1 = sV[a0 + 1];
                float q0 = sPQ[a0], q1 = sPQ[a0 + 1];
                en1 += v0 * tanh_fast(acc[mi][nj][0] + q0) + v1 * tanh_fast(acc[mi][nj][1] + q1);
                en2 += v0 * tanh_fast(acc[mi][nj][2] + q0) + v1 * tanh_fast(acc[mi][nj][3] + q1);
            }
            en1 += __shfl_xor_sync(0xffffffffu, en1, 1);
            en1 += __shfl_xor_sync(0xffffffffu, en1, 2);
            en2 += __shfl_xor_sync(0xffffffffu, en2, 1);
            en2 += __shfl_xor_sync(0xffffffffu, en2, 2);
            if ((l & 3) == 0) {
                int r1 = wt * 64 + mi * 16 + (l >> 2);
                sEn[wa * TM + r1] = en1;
                sEn[wa * TM + r1 + 8] = en2;
            }
        }
    }
    __syncthreads();
    if (tid < TM) {
        float* sEn = (float*)(smc + OFF_EN);
        float al = sEn[tid] + sEn[TM + tid] + sEn[2 * TM + tid] + sEn[3 * TM + tid] + vb[0];
        if (mask[b * T_ + tb + tid]) al += -1e25f;
        g_align[b * T_ + tb + tid] = al;
        ((float*)(smc + OFF_AL))[tid] = al;
    }
    __syncthreads();

    // ---- fused output GEMV partials: part[e] = sum_t align[t] * mem[b,tb+t,e] ----
    {
        const float* sAl = (const float*)(smc + OFF_AL);
        int e2 = tid * 2;
        float a0 = 0.f, a1 = 0.f;
        const float* mp = memB + e2;
#pragma unroll 8
        for (int t = 0; t < TM; t++) {
            float al = sAl[t];
            float2 m = *(const float2*)(mp + (size_t)t * E_);
            a0 = fmaf(al, m.x, a0);
            a1 = fmaf(al, m.y, a1);
        }
        float2 res; res.x = a0; res.y = a1;
        *(float2*)(g_part + (size_t)blockIdx.x * (B_ * E_) + b * E_ + e2) = res;
    }
}

// ---------------- softmax over T per batch -> attention_weights ----------------
__global__ void k_softmax(float* __restrict__ outw) {
    __shared__ float sE[T_];
    __shared__ float red[256];
    int b = blockIdx.x, tid = threadIdx.x;
    float mx = -3.4e38f;
    for (int i = tid; i < T_; i += 256) {
        float v = g_align[b * T_ + i];
        sE[i] = v;
        mx = fmaxf(mx, v);
    }
    red[tid] = mx;
    __syncthreads();
    for (int s = 128; s > 0; s >>= 1) {
        if (tid < s) red[tid] = fmaxf(red[tid], red[tid + s]);
        __syncthreads();
    }
    mx = red[0];
    __syncthreads();
    float sum = 0.f;
    for (int i = tid; i < T_; i += 256) {
        float ev = expf(sE[i] - mx);
        sE[i] = ev;
        sum += ev;
    }
    red[tid] = sum;
    __syncthreads();
    for (int s = 128; s > 0; s >>= 1) {
        if (tid < s) red[tid] += red[tid + s];
        __syncthreads();
    }
    float inv = 1.f / red[0];
    for (int i = tid; i < T_; i += 256) outw[b * T_ + i] = sE[i] * inv;
}

// ---------------- reduce GEMV partials ----------------
__global__ void k_reduce(float* __restrict__ outa) {
    int b = blockIdx.x, e = threadIdx.x;
    float s = 0.f;
#pragma unroll
    for (int p = 0; p < NPART; p++) s += g_part[(size_t)p * (B_ * E_) + b * E_ + e];
    outa[b * E_ + e] = s;
}

// ---------------- launch ----------------
extern "C" void kernel_launch(void* const* d_in, const int* in_sizes, int n_in,
                              void* d_out, int out_size) {
    (void)in_sizes; (void)n_in; (void)out_size;
    const float* hid  = (const float*)d_in[0];  // (B, R)
    const float* mem  = (const float*)d_in[1];  // (B, T, E)
    const float* aw   = (const float*)d_in[2];  // (B, 2, T)
    const int*   mask = (const int*)d_in[3];    // (B, T)
    const float* Wq   = (const float*)d_in[4];  // (R, A)
    const float* Wm   = (const float*)d_in[5];  // (E, A)
    const float* cw   = (const float*)d_in[6];  // (F, 2, K)
    const float* Wl   = (const float*)d_in[7];  // (F, A)
    const float* vw   = (const float*)d_in[8];  // (A,)
    const float* vb   = (const float*)d_in[9];  // (1,)

    float* out      = (float*)d_out;
    float* out_attn = out;              // (B, E)
    float* out_w    = out + B_ * E_;    // (B, T)

    static int configured = 0;
    if (!configured) {
        cudaFuncSetAttribute(k_main, cudaFuncAttributeMaxDynamicSharedMemorySize, SMEM_SZ);
        configured = 1;
    }

    k_pq<<<B_, 128>>>(hid, Wq);
    k_wcat<<<KTOT, 128>>>(Wm, cw, Wl);
    dim3 gm(T_ / TM, B_);
    k_main<<<gm, 256, SMEM_SZ>>>(mem, aw, mask, vw, vb);
    k_softmax<<<B_, 256>>>(out_w);
    k_reduce<<<B_, E_>>>(out_attn);
}

// round 12
// speedup vs baseline: 2.0608x; 1.3239x over previous
#include <cuda_runtime.h>
#include <cuda_fp16.h>
#include <math.h>
#include <stdint.h>

// Problem constants
#define B_   64
#define T_   2048
#define E_   512
#define R_   1024
#define A_   128
#define F_   32
#define KW   31
#define PADW 15
#define KIM  62
#define KTOT 576
#define KC2  64          // original-K per chunk
#define NCK  9           // 576/64
#define TM   128         // t rows per block
#define NPART 16         // T_/TM

typedef unsigned long long u64;

// Scratch (device globals; no allocations allowed)
__device__ float g_pq[B_ * A_];
__device__ __align__(16) __half g_Wh[A_ * KTOT];   // W^T fp16: [a][k]
__device__ float g_align[B_ * T_];
__device__ float g_part[NPART * B_ * E_];

// ---- dynamic smem layout: double-buffered A and B (fp16) ----
#define OFF_A0  0
#define OFF_A1  16384
#define OFF_B0  32768
#define OFF_B1  49152
#define OFF_PQ  65536
#define OFF_V   66048
#define OFF_AL  66560
#define OFF_EN  67072            // 4 x 128 x 4B
#define SMEM_SZ 69120            // x2 CTA = 138240 <= 228KB

__device__ __forceinline__ uint32_t smem_u32(const void* p) {
    uint32_t a;
    asm("{ .reg .u64 t; cvta.to.shared.u64 t, %1; cvt.u32.u64 %0, t; }" : "=r"(a) : "l"(p));
    return a;
}
// accurate tanh: 1 - 2/(e^{2x}+1) via ex2.approx + rcp.approx (~1e-6 rel)
__device__ __forceinline__ float tanh_fast(float x) {
    float e;
    asm("ex2.approx.f32 %0, %1;" : "=f"(e) : "f"(x * 2.885390081777927f));
    float r;
    asm("rcp.approx.f32 %0, %1;" : "=f"(r) : "f"(e + 1.0f));
    return fmaf(-2.0f, r, 1.0f);
}
__device__ __forceinline__ void ldsm4(uint32_t addr, uint32_t& r0, uint32_t& r1,
                                      uint32_t& r2, uint32_t& r3) {
    asm volatile("ldmatrix.sync.aligned.m8n8.x4.shared.b16 {%0,%1,%2,%3}, [%4];"
                 : "=r"(r0), "=r"(r1), "=r"(r2), "=r"(r3) : "r"(addr));
}
__device__ __forceinline__ void mma16816h(float* c, const uint32_t* a, uint32_t b0, uint32_t b1) {
    asm volatile(
        "mma.sync.aligned.m16n8k16.row.col.f32.f16.f16.f32 "
        "{%0,%1,%2,%3}, {%4,%5,%6,%7}, {%8,%9}, {%0,%1,%2,%3};"
        : "+f"(c[0]), "+f"(c[1]), "+f"(c[2]), "+f"(c[3])
        : "r"(a[0]), "r"(a[1]), "r"(a[2]), "r"(a[3]), "r"(b0), "r"(b1));
}
// pack two f32 -> f16x2: low half = x0, high half = x1
__device__ __forceinline__ uint32_t cvt_h2(float x1, float x0) {
    uint32_t r;
    asm("cvt.rn.f16x2.f32 %0, %1, %2;" : "=r"(r) : "f"(x1), "f"(x0));
    return r;
}

// ---------------- pq = attention_hidden @ W_query : (B, A) ----------------
__global__ void k_pq(const float* __restrict__ hid, const float* __restrict__ Wq) {
    __shared__ float sh[R_];
    int b = blockIdx.x, tid = threadIdx.x;
    for (int i = tid; i < R_; i += 128) sh[i] = hid[b * R_ + i];
    __syncthreads();
    float acc = 0.f;
#pragma unroll 8
    for (int r = 0; r < R_; r++) acc += sh[r] * Wq[r * A_ + tid];
    g_pq[b * A_ + tid] = acc;
}

// ---- Wcat^T fp16: k<512 = W_memory, 512..573 = conv.W_loc, rest 0 ----
__global__ void k_wcat(const float* __restrict__ Wm, const float* __restrict__ cw,
                       const float* __restrict__ Wl) {
    int row = blockIdx.x;  // k: 0..575
    int a = threadIdx.x;   // 0..127
    float v = 0.f;
    if (row < E_) {
        v = Wm[row * A_ + a];
    } else if (row < E_ + KIM) {
        int ck = row - E_;
        int c = ck / KW, k = ck - c * KW;
#pragma unroll
        for (int f = 0; f < F_; f++)
            v += cw[f * (2 * KW) + c * KW + k] * Wl[f * A_ + a];
    }
    g_Wh[a * KTOT + row] = __float2half_rn(v);
}

// ---------------- main: mma.sync fp16 single-pass GEMM + epilogue + fused GEMV ----------------
__global__ void __launch_bounds__(256, 2)
k_main(const float* __restrict__ mem, const float* __restrict__ aw,
       const int* __restrict__ mask, const float* __restrict__ vw,
       const float* __restrict__ vb) {
    extern __shared__ char smc[];
    uint32_t sb = smem_u32(smc);
    int tid = threadIdx.x;
    int l = tid & 31, w = tid >> 5;
    int wa = w & 3, wt = w >> 2;      // warp tile: 64t (wt) x 32a (wa)
    int b = blockIdx.y, tb = blockIdx.x * TM;

    if (tid < A_) {
        ((float*)(smc + OFF_PQ))[tid] = g_pq[b * A_ + tid];
        ((float*)(smc + OFF_V))[tid]  = vw[tid];
    }

    float acc[4][4][4];
#pragma unroll
    for (int i = 0; i < 4; i++)
#pragma unroll
        for (int j = 0; j < 4; j++)
#pragma unroll
            for (int k = 0; k < 4; k++) acc[i][j][k] = 0.f;

    const float* memB = mem + ((size_t)b * T_ + tb) * E_;
    const float* awB  = aw + (size_t)b * 2 * T_;

    // coalesced convert mapping: unit u (0..7): row = 16u + (tid>>4), col4 = tid&15
    int cvRow0 = tid >> 4;            // 0..15
    int cvCol4 = tid & 15;            // float4 index in 64-float chunk row
    const float* aCvtRow = memB + (size_t)cvRow0 * E_ + cvCol4 * 4;
    uint32_t cvRowBase = (uint32_t)cvRow0 * 128u;
    // per-thread-constant swizzled byte offset within the row
    uint32_t cvOff = (uint32_t)((((cvCol4 >> 1) ^ (cvRow0 & 7)) << 4) + (cvCol4 & 1) * 8);

    // B copy mapping: iter i (0..3): idx = i*256+tid -> n = idx>>3, q = idx&7
    int bcN = tid >> 3;               // +32 per iter
    int bcQ = tid & 7;

    // ldmatrix lane constants
    int rowA = wt * 64 + (l & 15);
    uint32_t aRowBase = (uint32_t)rowA * 128u;
    int aSwz = rowA & 7;
    int kpA = (l >> 4) & 1;
    int nB = wa * 32 + ((l & 16) >> 1) + (l & 7);
    uint32_t bRowBase = (uint32_t)nB * 128u;
    int bSwz = l & 7;
    int kpB = (l >> 3) & 1;

// load one float4 of chunk (cc), unit (uu) into f4_
#define LOADU(f4_, cc, uu) do {                                                 \
    if ((cc) < 8) {                                                             \
        f4_ = *(const float4*)(aCvtRow + (size_t)(uu) * (16 * E_) + (cc) * KC2); \
    } else {                                                                    \
        float t_[4];                                                            \
        _Pragma("unroll")                                                       \
        for (int j_ = 0; j_ < 4; j_++) {                                        \
            int kk_ = cvCol4 * 4 + j_;                                          \
            float v_ = 0.f;                                                     \
            if (kk_ < KIM) {                                                    \
                int ci_ = (kk_ >= KW) ? 1 : 0;                                  \
                int kp_ = kk_ - ci_ * KW;                                       \
                int tg_ = tb + cvRow0 + 16 * (uu) + kp_ - PADW;                 \
                if (tg_ >= 0 && tg_ < T_) v_ = awB[ci_ * T_ + tg_];             \
            }                                                                   \
            t_[j_] = v_;                                                        \
        }                                                                       \
        f4_.x = t_[0]; f4_.y = t_[1]; f4_.z = t_[2]; f4_.w = t_[3];             \
    }                                                                           \
} while (0)

// convert float4 to 4 fp16 and store swizzled (STS.64) into buffer (bufOff), unit (uu)
#define CVTSTORE(f4_, uu, bufOff) do {                                          \
    uint2 h_;                                                                   \
    h_.x = cvt_h2(f4_.y, f4_.x);                                                \
    h_.y = cvt_h2(f4_.w, f4_.z);                                                \
    *(uint2*)(smc + (bufOff) + cvRowBase + (uint32_t)(uu) * 2048u + cvOff) = h_; \
} while (0)

// B load iter (ii) of chunk (cc) into uint4 w_
#define BLOAD(w_, cc, ii) do {                                                  \
    int n_ = bcN + (ii) * 32;                                                   \
    w_ = *(const uint4*)((const char*)g_Wh + (size_t)n_ * (KTOT * 2) + (cc) * 128 + bcQ * 16); \
} while (0)
// B store iter (ii) into buffer (bufOff)
#define BSTORE(w_, ii, bufOff) do {                                             \
    int n_ = bcN + (ii) * 32;                                                   \
    uint32_t off_ = (uint32_t)n_ * 128u + (uint32_t)(((bcQ ^ (n_ & 7)) << 4));  \
    *(uint4*)(smc + (bufOff) + off_) = w_;                                      \
} while (0)

    // ---- prologue: convert A(0) -> A0, copy B(0) -> B0 ----
    {
        float4 f;
#pragma unroll
        for (int u = 0; u < 8; u++) { LOADU(f, 0, u); CVTSTORE(f, u, OFF_A0); }
        uint4 wv;
#pragma unroll
        for (int i = 0; i < 4; i++) { BLOAD(wv, 0, i); BSTORE(wv, i, OFF_B0); }
    }
    __syncthreads();

#pragma unroll 1
    for (int c = 0; c < NCK; c++) {
        uint32_t curA = (c & 1) ? OFF_A1 : OFF_A0;
        uint32_t nxtA = (c & 1) ? OFF_A0 : OFF_A1;
        uint32_t curB = (c & 1) ? OFF_B1 : OFF_B0;
        uint32_t nxtB = (c & 1) ? OFF_B0 : OFF_B1;
        int doNext = (c + 1 < NCK);

        // ---- compute + interleaved prefetch/convert of chunk c+1 ----
#pragma unroll
        for (int s = 0; s < 4; s++) {
            float4 f0, f1;
            uint4 wv;
            if (doNext) {
                LOADU(f0, c + 1, 2 * s);
                LOADU(f1, c + 1, 2 * s + 1);
                BLOAD(wv, c + 1, s);
            }
            uint32_t bh[8];
            uint32_t kbB = (uint32_t)((((2 * s + kpB) ^ bSwz) << 4));
            ldsm4(sb + curB + bRowBase + kbB,          bh[0], bh[1], bh[2], bh[3]);
            ldsm4(sb + curB + bRowBase + 2048u + kbB,  bh[4], bh[5], bh[6], bh[7]);
            uint32_t kbA = (uint32_t)((((2 * s + kpA) ^ aSwz) << 4));
#pragma unroll
            for (int mi = 0; mi < 4; mi++) {
                uint32_t ah[4];
                ldsm4(sb + curA + aRowBase + mi * 2048u + kbA, ah[0], ah[1], ah[2], ah[3]);
                mma16816h(acc[mi][0], ah, bh[0], bh[1]);
                mma16816h(acc[mi][1], ah, bh[2], bh[3]);
                mma16816h(acc[mi][2], ah, bh[4], bh[5]);
                mma16816h(acc[mi][3], ah, bh[6], bh[7]);
            }
            if (doNext) {
                CVTSTORE(f0, 2 * s, nxtA);
                CVTSTORE(f1, 2 * s + 1, nxtA);
                BSTORE(wv, s, nxtB);
            }
        }
        __syncthreads();   // cur fully consumed; nxt fully written
    }
#undef LOADU
#undef CVTSTORE
#undef BLOAD
#undef BSTORE

    // ---- epilogue: en[t] = sum_a v[a] * tanh(D[t,a] + pq[a]) ----
    {
        const float* sPQ = (const float*)(smc + OFF_PQ);
        const float* sV  = (const float*)(smc + OFF_V);
        float* sEn = (float*)(smc + OFF_EN);   // [4 wa][128 t]
#pragma unroll
        for (int mi = 0; mi < 4; mi++) {
            float en1 = 0.f, en2 = 0.f;
#pragma unroll
            for (int nj = 0; nj < 4; nj++) {
                int a0 = wa * 32 + nj * 8 + 2 * (l & 3);
                float v0 = sV[a0], v1 = sV[a0 + 1];
                float q0 = sPQ[a0], q1 = sPQ[a0 + 1];
                en1 += v0 * tanh_fast(acc[mi][nj][0] + q0) + v1 * tanh_fast(acc[mi][nj][1] + q1);
                en2 += v0 * tanh_fast(acc[mi][nj][2] + q0) + v1 * tanh_fast(acc[mi][nj][3] + q1);
            }
            en1 += __shfl_xor_sync(0xffffffffu, en1, 1);
            en1 += __shfl_xor_sync(0xffffffffu, en1, 2);
            en2 += __shfl_xor_sync(0xffffffffu, en2, 1);
            en2 += __shfl_xor_sync(0xffffffffu, en2, 2);
            if ((l & 3) == 0) {
                int r1 = wt * 64 + mi * 16 + (l >> 2);
                sEn[wa * TM + r1] = en1;
                sEn[wa * TM + r1 + 8] = en2;
            }
        }
    }
    __syncthreads();
    if (tid < TM) {
        float* sEn = (float*)(smc + OFF_EN);
        float al = sEn[tid] + sEn[TM + tid] + sEn[2 * TM + tid] + sEn[3 * TM + tid] + vb[0];
        if (mask[b * T_ + tb + tid]) al += -1e25f;
        g_align[b * T_ + tb + tid] = al;
        ((float*)(smc + OFF_AL))[tid] = al;
    }
    __syncthreads();

    // ---- fused output GEMV partials: part[e] = sum_t align[t] * mem[b,tb+t,e] ----
    {
        const float* sAl = (const float*)(smc + OFF_AL);
        int e2 = tid * 2;
        float a0 = 0.f, a1 = 0.f;
        const float* mp = memB + e2;
#pragma unroll 8
        for (int t = 0; t < TM; t++) {
            float al = sAl[t];
            float2 m = *(const float2*)(mp + (size_t)t * E_);
            a0 = fmaf(al, m.x, a0);
            a1 = fmaf(al, m.y, a1);
        }
        float2 res; res.x = a0; res.y = a1;
        *(float2*)(g_part + (size_t)blockIdx.x * (B_ * E_) + b * E_ + e2) = res;
    }
}

// ---------------- softmax over T per batch -> attention_weights ----------------
__global__ void k_softmax(float* __restrict__ outw) {
    __shared__ float sE[T_];
    __shared__ float red[256];
    int b = blockIdx.x, tid = threadIdx.x;
    float mx = -3.4e38f;
    for (int i = tid; i < T_; i += 256) {
        float v = g_align[b * T_ + i];
        sE[i] = v;
        mx = fmaxf(mx, v);
    }
    red[tid] = mx;
    __syncthreads();
    for (int s = 128; s > 0; s >>= 1) {
        if (tid < s) red[tid] = fmaxf(red[tid], red[tid + s]);
        __syncthreads();
    }
    mx = red[0];
    __syncthreads();
    float sum = 0.f;
    for (int i = tid; i < T_; i += 256) {
        float ev = expf(sE[i] - mx);
        sE[i] = ev;
        sum += ev;
    }
    red[tid] = sum;
    __syncthreads();
    for (int s = 128; s > 0; s >>= 1) {
        if (tid < s) red[tid] += red[tid + s];
        __syncthreads();
    }
    float inv = 1.f / red[0];
    for (int i = tid; i < T_; i += 256) outw[b * T_ + i] = sE[i] * inv;
}

// ---------------- reduce GEMV partials ----------------
__global__ void k_reduce(float* __restrict__ outa) {
    int b = blockIdx.x, e = threadIdx.x;
    float s = 0.f;
#pragma unroll
    for (int p = 0; p < NPART; p++) s += g_part[(size_t)p * (B_ * E_) + b * E_ + e];
    outa[b * E_ + e] = s;
}

// ---------------- launch ----------------
extern "C" void kernel_launch(void* const* d_in, const int* in_sizes, int n_in,
                              void* d_out, int out_size) {
    (void)in_sizes; (void)n_in; (void)out_size;
    const float* hid  = (const float*)d_in[0];  // (B, R)
    const float* mem  = (const float*)d_in[1];  // (B, T, E)
    const float* aw   = (const float*)d_in[2];  // (B, 2, T)
    const int*   mask = (const int*)d_in[3];    // (B, T)
    const float* Wq   = (const float*)d_in[4];  // (R, A)
    const float* Wm   = (const float*)d_in[5];  // (E, A)
    const float* cw   = (const float*)d_in[6];  // (F, 2, K)
    const float* Wl   = (const float*)d_in[7];  // (F, A)
    const float* vw   = (const float*)d_in[8];  // (A,)
    const float* vb   = (const float*)d_in[9];  // (1,)

    float* out      = (float*)d_out;
    float* out_attn = out;              // (B, E)
    float* out_w    = out + B_ * E_;    // (B, T)

    static int configured = 0;
    if (!configured) {
        cudaFuncSetAttribute(k_main, cudaFuncAttributeMaxDynamicSharedMemorySize, SMEM_SZ);
        configured = 1;
    }

    k_pq<<<B_, 128>>>(hid, Wq);
    k_wcat<<<KTOT, 128>>>(Wm, cw, Wl);
    dim3 gm(T_ / TM, B_);
    k_main<<<gm, 256, SMEM_SZ>>>(mem, aw, mask, vw, vb);
    k_softmax<<<B_, 256>>>(out_w);
    k_reduce<<<B_, E_>>>(out_attn);
}